// round 1
// baseline (speedup 1.0000x reference)
#include <cuda_runtime.h>
#include <cuda_bf16.h>
#include <math.h>

// Problem constants
#define B_    8
#define CIN   128
#define H_    64
#define W_    64
#define HW    (H_ * W_)        // 4096
#define COUT  256
#define KK9   9
#define OC18  18
#define KD    (CIN * KK9)      // 1152

// ---------------- scratch (device globals; no allocation allowed) -----------
__device__ float g_off[B_ * OC18 * HW];          // offsets [b][18][4096]
__device__ float g_P[(size_t)B_ * KD * HW];      // deformable im2col [b][1152][4096]
__device__ float g_mean[COUT];
__device__ float g_rstd[COUT];

// ============================================================================
// Kernel A: offset conv (direct, 3x3, pad 1). One thread = one pixel, all 18
// output channels accumulated in registers; weights staged in dynamic smem.
// ============================================================================
__global__ void offset_conv_kernel(const float* __restrict__ x,
                                   const float* __restrict__ w,
                                   const float* __restrict__ bias) {
    extern __shared__ float ws[];   // [18][128][9] = 20736 floats
    for (int i = threadIdx.x; i < OC18 * KD; i += blockDim.x) ws[i] = w[i];
    __syncthreads();

    int gid = blockIdx.x * blockDim.x + threadIdx.x;   // < 32768
    int b   = gid >> 12;
    int pix = gid & 4095;
    int y   = pix >> 6;
    int xx  = pix & 63;

    float acc[OC18];
#pragma unroll
    for (int oc = 0; oc < OC18; oc++) acc[oc] = bias[oc];

    const float* xb = x + (size_t)b * CIN * HW;
    for (int c = 0; c < CIN; c++) {
        const float* xc = xb + (size_t)c * HW;
        float v[9];
#pragma unroll
        for (int ky = 0; ky < 3; ky++) {
            int yy = y - 1 + ky;
            bool yv = (unsigned)yy < (unsigned)H_;
#pragma unroll
            for (int kx = 0; kx < 3; kx++) {
                int xx2 = xx - 1 + kx;
                bool xv = (unsigned)xx2 < (unsigned)W_;
                v[ky * 3 + kx] = (yv && xv) ? xc[yy * W_ + xx2] : 0.f;
            }
        }
#pragma unroll
        for (int kk = 0; kk < 9; kk++) {
            float xvv = v[kk];
#pragma unroll
            for (int oc = 0; oc < OC18; oc++)
                acc[oc] = fmaf(xvv, ws[oc * KD + c * 9 + kk], acc[oc]);
        }
    }

    float* ob = g_off + (size_t)b * OC18 * HW + pix;
#pragma unroll
    for (int oc = 0; oc < OC18; oc++) ob[(size_t)oc * HW] = acc[oc];
}

// ============================================================================
// Kernel B: deformable bilinear gather -> P[b][c*9+kk][n].
// One thread = one (b, kk, pixel); loops over 128 channels.
// ============================================================================
__global__ void gather_kernel(const float* __restrict__ x,
                              float* __restrict__ P) {
    int gid = blockIdx.x * blockDim.x + threadIdx.x;   // < 294912
    int n   = gid & 4095;
    int t   = gid >> 12;           // b*9 + kk
    int kk  = t % 9;
    int b   = t / 9;
    int y   = n >> 6;
    int xx  = n & 63;

    const float* offb = g_off + (size_t)b * OC18 * HW;
    float dy = offb[(size_t)(2 * kk + 0) * HW + n];
    float dx = offb[(size_t)(2 * kk + 1) * HW + n];

    float sy = (float)(y - 1 + kk / 3) + dy;
    float sx = (float)(xx - 1 + kk % 3) + dx;

    float fy = floorf(sy), fx = floorf(sx);
    int y0 = (int)fy, x0 = (int)fx;
    int y1 = y0 + 1, x1 = x0 + 1;
    float wy = sy - fy, wx = sx - fx;

    bool vy0 = (unsigned)y0 < (unsigned)H_;
    bool vy1 = (unsigned)y1 < (unsigned)H_;
    bool vx0 = (unsigned)x0 < (unsigned)W_;
    bool vx1 = (unsigned)x1 < (unsigned)W_;

    int cy0 = min(max(y0, 0), H_ - 1), cy1 = min(max(y1, 0), H_ - 1);
    int cx0 = min(max(x0, 0), W_ - 1), cx1 = min(max(x1, 0), W_ - 1);

    int i00 = cy0 * W_ + cx0;
    int i01 = cy0 * W_ + cx1;
    int i10 = cy1 * W_ + cx0;
    int i11 = cy1 * W_ + cx1;

    float w00 = (1.f - wy) * (1.f - wx) * (float)(vy0 && vx0);
    float w01 = (1.f - wy) * wx         * (float)(vy0 && vx1);
    float w10 = wy * (1.f - wx)         * (float)(vy1 && vx0);
    float w11 = wy * wx                 * (float)(vy1 && vx1);

    const float* xb = x + (size_t)b * CIN * HW;
    float* pb = P + ((size_t)b * CIN * KK9 + kk) * HW + n;

#pragma unroll 4
    for (int c = 0; c < CIN; c++) {
        const float* xc = xb + (size_t)c * HW;
        float v = w00 * xc[i00] + w01 * xc[i01] + w10 * xc[i10] + w11 * xc[i11];
        pb[(size_t)c * KK9 * HW] = v;
    }
}

// ============================================================================
// Kernel C: SGEMM  Y[b] = Wc[256,1152] @ P[b][1152,4096] + bias
// 128x128 tile, BK=16, 256 threads, 8x8 micro-tile per thread.
// ============================================================================
#define BM 128
#define BN 128
#define BKT 16

__global__ void gemm_kernel(const float* __restrict__ Wc,
                            const float* __restrict__ P,
                            const float* __restrict__ bias,
                            float* __restrict__ Y) {
    __shared__ float As[BKT][BM];
    __shared__ float Bs[BKT][BN];

    int tid = threadIdx.x;            // 256
    int bn  = blockIdx.x * BN;
    int bm  = blockIdx.y * BM;
    int b   = blockIdx.z;

    const float* Pb = P + (size_t)b * KD * HW;

    float acc[8][8];
#pragma unroll
    for (int i = 0; i < 8; i++)
#pragma unroll
        for (int j = 0; j < 8; j++) acc[i][j] = 0.f;

    int ty = tid >> 4;   // 0..15
    int tx = tid & 15;   // 0..15

    for (int k0 = 0; k0 < KD; k0 += BKT) {
        // Load A tile (transposed into smem): 128 x 16
#pragma unroll
        for (int i = 0; i < 2; i++) {
            int idx = tid + i * 256;
            int m   = idx >> 2;             // 0..127
            int kq  = (idx & 3) << 2;       // 0,4,8,12
            float4 v = *(const float4*)(Wc + (size_t)(bm + m) * KD + k0 + kq);
            As[kq + 0][m] = v.x;
            As[kq + 1][m] = v.y;
            As[kq + 2][m] = v.z;
            As[kq + 3][m] = v.w;
        }
        // Load B tile: 16 x 128
#pragma unroll
        for (int i = 0; i < 2; i++) {
            int idx = tid + i * 256;
            int k   = idx >> 5;             // 0..15
            int nq  = (idx & 31) << 2;      // 0..124
            *(float4*)&Bs[k][nq] =
                *(const float4*)(Pb + (size_t)(k0 + k) * HW + bn + nq);
        }
        __syncthreads();

#pragma unroll
        for (int k = 0; k < BKT; k++) {
            float a[8], bv[8];
            *(float4*)&a[0]  = *(const float4*)&As[k][ty * 8];
            *(float4*)&a[4]  = *(const float4*)&As[k][ty * 8 + 4];
            *(float4*)&bv[0] = *(const float4*)&Bs[k][tx * 8];
            *(float4*)&bv[4] = *(const float4*)&Bs[k][tx * 8 + 4];
#pragma unroll
            for (int i = 0; i < 8; i++)
#pragma unroll
                for (int j = 0; j < 8; j++)
                    acc[i][j] = fmaf(a[i], bv[j], acc[i][j]);
        }
        __syncthreads();
    }

    // Epilogue: add bias, write to Y
#pragma unroll
    for (int i = 0; i < 8; i++) {
        int m = bm + ty * 8 + i;
        float bb = bias[m];
        float* yp = Y + ((size_t)b * COUT + m) * HW + bn + tx * 8;
        float4 v0, v1;
        v0.x = acc[i][0] + bb; v0.y = acc[i][1] + bb;
        v0.z = acc[i][2] + bb; v0.w = acc[i][3] + bb;
        v1.x = acc[i][4] + bb; v1.y = acc[i][5] + bb;
        v1.z = acc[i][6] + bb; v1.w = acc[i][7] + bb;
        *(float4*)(yp)     = v0;
        *(float4*)(yp + 4) = v1;
    }
}

// ============================================================================
// Kernel D: BN stats (mean / rstd per channel, biased variance, over B*H*W)
// ============================================================================
__global__ void bnstats_kernel(const float* __restrict__ Y) {
    int o = blockIdx.x;
    int tid = threadIdx.x;
    float s = 0.f, s2 = 0.f;
    for (int b = 0; b < B_; b++) {
        const float* p = Y + ((size_t)b * COUT + o) * HW;
        for (int n = tid; n < HW; n += 256) {
            float v = p[n];
            s += v;
            s2 = fmaf(v, v, s2);
        }
    }
    __shared__ float sh[256], sh2[256];
    sh[tid] = s; sh2[tid] = s2;
    __syncthreads();
    for (int st = 128; st > 0; st >>= 1) {
        if (tid < st) { sh[tid] += sh[tid + st]; sh2[tid] += sh2[tid + st]; }
        __syncthreads();
    }
    if (tid == 0) {
        const float invN = 1.f / (float)(B_ * HW);
        float m  = sh[0] * invN;
        float var = sh2[0] * invN - m * m;
        g_mean[o] = m;
        g_rstd[o] = rsqrtf(var + 1e-5f);
    }
}

// ============================================================================
// Kernel E: normalize + affine + SiLU, in place on d_out (float4 vectorized)
// ============================================================================
__global__ void bnsilu_kernel(float* __restrict__ Y,
                              const float* __restrict__ gamma,
                              const float* __restrict__ beta) {
    size_t i4 = (size_t)blockIdx.x * blockDim.x + threadIdx.x;  // < 2097152
    int o = (int)((i4 >> 10) & (COUT - 1));
    float m = g_mean[o], r = g_rstd[o], g = gamma[o], be = beta[o];
    float4 v = ((float4*)Y)[i4];
    float t;
    t = (v.x - m) * r * g + be; v.x = t / (1.f + expf(-t));
    t = (v.y - m) * r * g + be; v.y = t / (1.f + expf(-t));
    t = (v.z - m) * r * g + be; v.z = t / (1.f + expf(-t));
    t = (v.w - m) * r * g + be; v.w = t / (1.f + expf(-t));
    ((float4*)Y)[i4] = v;
}

// ============================================================================
// Launch
// ============================================================================
extern "C" void kernel_launch(void* const* d_in, const int* in_sizes, int n_in,
                              void* d_out, int out_size) {
    const float* x        = (const float*)d_in[0];   // [8,128,64,64]
    const float* offset_w = (const float*)d_in[1];   // [18,128,3,3]
    const float* offset_b = (const float*)d_in[2];   // [18]
    const float* dconv_w  = (const float*)d_in[3];   // [256,128,3,3]
    const float* dconv_b  = (const float*)d_in[4];   // [256]
    const float* bn_gamma = (const float*)d_in[5];   // [256]
    const float* bn_beta  = (const float*)d_in[6];   // [256]
    float* out = (float*)d_out;                      // [8,256,64,64]

    float* P;
    cudaGetSymbolAddress((void**)&P, g_P);

    // A: offset conv — 32768 pixels, 128 thr/block, 18*1152 floats dyn smem
    static bool attr_set = false;
    if (!attr_set) {
        cudaFuncSetAttribute(offset_conv_kernel,
                             cudaFuncAttributeMaxDynamicSharedMemorySize,
                             OC18 * KD * (int)sizeof(float));
        attr_set = true;
    }
    offset_conv_kernel<<<256, 128, OC18 * KD * sizeof(float)>>>(x, offset_w, offset_b);

    // B: deformable gather — 8*9*4096 threads
    gather_kernel<<<(B_ * KK9 * HW) / 256, 256>>>(x, P);

    // C: GEMM — grid (N/128, M/128, B)
    dim3 g(HW / BN, COUT / BM, B_);
    gemm_kernel<<<g, 256>>>(dconv_w, P, dconv_b, out);

    // D: BN stats
    bnstats_kernel<<<COUT, 256>>>(out);

    // E: normalize + SiLU in place
    bnsilu_kernel<<<(B_ * COUT * HW / 4) / 256, 256>>>(out, bn_gamma, bn_beta);
}

// round 3
// speedup vs baseline: 1.4957x; 1.4957x over previous
#include <cuda_runtime.h>
#include <cuda_bf16.h>
#include <math.h>
#include <cstdint>

// Problem constants
#define B_    8
#define CIN   128
#define H_    64
#define W_    64
#define HW    (H_ * W_)        // 4096
#define COUT  256
#define KK9   9
#define OC18  18
#define KD    (CIN * KK9)      // 1152

// ---------------- scratch (device globals; no allocation allowed) -----------
__device__ float g_off[B_ * OC18 * HW];                       // offsets
__device__ __nv_bfloat16 g_Phi[(size_t)B_ * KD * HW];         // P hi [b][k][n]
__device__ __nv_bfloat16 g_Plo[(size_t)B_ * KD * HW];         // P lo
__device__ __nv_bfloat16 g_Whi[COUT * KD];                    // W hi [m][k]
__device__ __nv_bfloat16 g_Wlo[COUT * KD];
__device__ float g_mean[COUT];
__device__ float g_rstd[COUT];

// ============================================================================
// PTX helpers (all plain sm_80+ instructions — compile for compute_103)
// ============================================================================
__device__ __forceinline__ uint32_t smem_u32(const void* p) {
    uint32_t a;
    asm("{ .reg .u64 t; cvta.to.shared.u64 t, %1; cvt.u32.u64 %0, t; }"
        : "=r"(a) : "l"(p));
    return a;
}
__device__ __forceinline__ void cpa16(uint32_t s, const void* g) {
    asm volatile("cp.async.cg.shared.global [%0], [%1], 16;" :: "r"(s), "l"(g));
}
#define CPA_COMMIT() asm volatile("cp.async.commit_group;" ::: "memory")
#define CPA_WAIT(N)  asm volatile("cp.async.wait_group %0;" :: "n"(N) : "memory")

__device__ __forceinline__ void ldsm4(uint32_t* r, uint32_t a) {
    asm volatile("ldmatrix.sync.aligned.m8n8.x4.shared.b16 {%0,%1,%2,%3}, [%4];"
                 : "=r"(r[0]), "=r"(r[1]), "=r"(r[2]), "=r"(r[3]) : "r"(a));
}
__device__ __forceinline__ void ldsm4t(uint32_t& r0, uint32_t& r1,
                                       uint32_t& r2, uint32_t& r3, uint32_t a) {
    asm volatile("ldmatrix.sync.aligned.m8n8.x4.trans.shared.b16 {%0,%1,%2,%3}, [%4];"
                 : "=r"(r0), "=r"(r1), "=r"(r2), "=r"(r3) : "r"(a));
}
__device__ __forceinline__ void mma16816(float* d, const uint32_t* a,
                                         const uint32_t* b) {
    asm volatile(
        "mma.sync.aligned.m16n8k16.row.col.f32.bf16.bf16.f32 "
        "{%0,%1,%2,%3}, {%4,%5,%6,%7}, {%8,%9}, {%0,%1,%2,%3};"
        : "+f"(d[0]), "+f"(d[1]), "+f"(d[2]), "+f"(d[3])
        : "r"(a[0]), "r"(a[1]), "r"(a[2]), "r"(a[3]), "r"(b[0]), "r"(b[1]));
}

// ============================================================================
// Kernel A: offset conv (direct 3x3, pad 1) — unchanged (known good)
// ============================================================================
__global__ void offset_conv_kernel(const float* __restrict__ x,
                                   const float* __restrict__ w,
                                   const float* __restrict__ bias) {
    extern __shared__ float ws[];
    for (int i = threadIdx.x; i < OC18 * KD; i += blockDim.x) ws[i] = w[i];
    __syncthreads();

    int gid = blockIdx.x * blockDim.x + threadIdx.x;
    int b   = gid >> 12;
    int pix = gid & 4095;
    int y   = pix >> 6;
    int xx  = pix & 63;

    float acc[OC18];
#pragma unroll
    for (int oc = 0; oc < OC18; oc++) acc[oc] = bias[oc];

    const float* xb = x + (size_t)b * CIN * HW;
    for (int c = 0; c < CIN; c++) {
        const float* xc = xb + (size_t)c * HW;
        float v[9];
#pragma unroll
        for (int ky = 0; ky < 3; ky++) {
            int yy = y - 1 + ky;
            bool yv = (unsigned)yy < (unsigned)H_;
#pragma unroll
            for (int kx = 0; kx < 3; kx++) {
                int x2 = xx - 1 + kx;
                bool xv = (unsigned)x2 < (unsigned)W_;
                v[ky * 3 + kx] = (yv && xv) ? xc[yy * W_ + x2] : 0.f;
            }
        }
#pragma unroll
        for (int kk = 0; kk < 9; kk++) {
            float xvv = v[kk];
#pragma unroll
            for (int oc = 0; oc < OC18; oc++)
                acc[oc] = fmaf(xvv, ws[oc * KD + c * 9 + kk], acc[oc]);
        }
    }

    float* ob = g_off + (size_t)b * OC18 * HW + pix;
#pragma unroll
    for (int oc = 0; oc < OC18; oc++) ob[(size_t)oc * HW] = acc[oc];
}

// ============================================================================
// Kernel B: deformable bilinear gather -> P_hi/P_lo (bf16 split) [b][k][n]
// ============================================================================
__global__ void gather_kernel(const float* __restrict__ x,
                              __nv_bfloat16* __restrict__ Phi,
                              __nv_bfloat16* __restrict__ Plo) {
    int gid = blockIdx.x * blockDim.x + threadIdx.x;
    int n   = gid & 4095;
    int t   = gid >> 12;
    int kk  = t % 9;
    int b   = t / 9;
    int y   = n >> 6;
    int xx  = n & 63;

    const float* offb = g_off + (size_t)b * OC18 * HW;
    float dy = offb[(size_t)(2 * kk + 0) * HW + n];
    float dx = offb[(size_t)(2 * kk + 1) * HW + n];

    float sy = (float)(y - 1 + kk / 3) + dy;
    float sx = (float)(xx - 1 + kk % 3) + dx;

    float fy = floorf(sy), fx = floorf(sx);
    int y0 = (int)fy, x0 = (int)fx;
    int y1 = y0 + 1, x1 = x0 + 1;
    float wy = sy - fy, wx = sx - fx;

    bool vy0 = (unsigned)y0 < (unsigned)H_;
    bool vy1 = (unsigned)y1 < (unsigned)H_;
    bool vx0 = (unsigned)x0 < (unsigned)W_;
    bool vx1 = (unsigned)x1 < (unsigned)W_;

    int cy0 = min(max(y0, 0), H_ - 1), cy1 = min(max(y1, 0), H_ - 1);
    int cx0 = min(max(x0, 0), W_ - 1), cx1 = min(max(x1, 0), W_ - 1);

    int i00 = cy0 * W_ + cx0;
    int i01 = cy0 * W_ + cx1;
    int i10 = cy1 * W_ + cx0;
    int i11 = cy1 * W_ + cx1;

    float w00 = (1.f - wy) * (1.f - wx) * (float)(vy0 && vx0);
    float w01 = (1.f - wy) * wx         * (float)(vy0 && vx1);
    float w10 = wy * (1.f - wx)         * (float)(vy1 && vx0);
    float w11 = wy * wx                 * (float)(vy1 && vx1);

    const float* xb = x + (size_t)b * CIN * HW;
    size_t base = ((size_t)b * KD + kk) * HW + n;

#pragma unroll 4
    for (int c = 0; c < CIN; c++) {
        const float* xc = xb + (size_t)c * HW;
        float v = w00 * xc[i00] + w01 * xc[i01] + w10 * xc[i10] + w11 * xc[i11];
        __nv_bfloat16 h = __float2bfloat16(v);
        float lo = v - __bfloat162float(h);
        size_t idx = base + (size_t)c * (KK9 * HW);
        Phi[idx] = h;
        Plo[idx] = __float2bfloat16(lo);
    }
}

// ============================================================================
// Kernel B2: split dconv weights into bf16 hi/lo
// ============================================================================
__global__ void wsplit_kernel(const float* __restrict__ w,
                              __nv_bfloat16* __restrict__ hi,
                              __nv_bfloat16* __restrict__ lo) {
    int i = blockIdx.x * blockDim.x + threadIdx.x;
    float v = w[i];
    __nv_bfloat16 h = __float2bfloat16(v);
    hi[i] = h;
    lo[i] = __float2bfloat16(v - __bfloat162float(h));
}

// ============================================================================
// Kernel C: HMMA GEMM  Y[b] = W[256,1152] @ P[b][1152,4096] + bias
// bf16 hi/lo 3-pass (Ah*Bh + Ah*Bl + Al*Bh), fp32 accum.
// CTA 128x128, BK=32, 8 warps (2x4, warp tile 64x32), cp.async double buffer.
// ============================================================================
#define BK      32
#define NC      (KD / BK)        // 36
#define A_STR   40               // padded bf16 per A row (32 + 8)
#define B_STR   136              // padded bf16 per B row (128 + 8)
#define AH_OFF  0
#define AL_OFF  (128 * A_STR)                // 5120
#define BH_OFF  (2 * 128 * A_STR)            // 10240
#define BL_OFF  (BH_OFF + 32 * B_STR)        // 14592
#define STG     (BL_OFF + 32 * B_STR)        // 18944 bf16 per stage
#define SMEM_GEMM (2 * STG * 2)              // bytes = 75776

__global__ void __launch_bounds__(256, 1)
gemm_mma_kernel(const __nv_bfloat16* __restrict__ Whi,
                const __nv_bfloat16* __restrict__ Wlo,
                const __nv_bfloat16* __restrict__ Phi,
                const __nv_bfloat16* __restrict__ Plo,
                const float* __restrict__ bias,
                float* __restrict__ Y) {
    extern __shared__ __nv_bfloat16 sm[];
    const uint32_t sbase = smem_u32(sm);

    int tid  = threadIdx.x;
    int wid  = tid >> 5;
    int lane = tid & 31;
    int bn = blockIdx.x * 128;
    int bm = blockIdx.y * 128;
    int b  = blockIdx.z;

    int wm = (wid >> 2) * 64;    // warp m offset in tile
    int wn = (wid & 3) * 32;     // warp n offset in tile

    const __nv_bfloat16* PbH = Phi + (size_t)b * KD * HW;
    const __nv_bfloat16* PbL = Plo + (size_t)b * KD * HW;

    float acc[4][4][4];
#pragma unroll
    for (int i = 0; i < 4; i++)
#pragma unroll
        for (int j = 0; j < 4; j++)
#pragma unroll
            for (int q = 0; q < 4; q++) acc[i][j][q] = 0.f;

    // --- async stage loader ---
    auto load_stage = [&](int chunk, int st) {
        int k0 = chunk * BK;
        uint32_t s0 = sbase + (uint32_t)(st * STG) * 2;
        // A: 128 rows x 32 k, hi+lo
#pragma unroll
        for (int i = 0; i < 2; i++) {
            int idx = tid + i * 256;          // 0..511
            int m   = idx >> 2;               // 0..127
            int kq  = (idx & 3) << 3;         // 0,8,16,24
            size_t go = (size_t)(bm + m) * KD + k0 + kq;
            uint32_t sa = s0 + (uint32_t)(m * A_STR + kq) * 2;
            cpa16(sa + AH_OFF * 2, Whi + go);
            cpa16(sa + AL_OFF * 2, Wlo + go);
        }
        // B: 32 k-rows x 128 n, hi+lo
#pragma unroll
        for (int i = 0; i < 2; i++) {
            int idx = tid + i * 256;
            int k   = idx >> 4;               // 0..31
            int nq  = (idx & 15) << 3;        // 0..120
            size_t go = (size_t)(k0 + k) * HW + bn + nq;
            uint32_t sa = s0 + (uint32_t)(k * B_STR + nq) * 2;
            cpa16(sa + BH_OFF * 2, PbH + go);
            cpa16(sa + BL_OFF * 2, PbL + go);
        }
        CPA_COMMIT();
    };

    load_stage(0, 0);

    for (int c = 0; c < NC; c++) {
        int st = c & 1;
        if (c + 1 < NC) {
            load_stage(c + 1, st ^ 1);
            CPA_WAIT(1);
        } else {
            CPA_WAIT(0);
        }
        __syncthreads();

        uint32_t s0 = sbase + (uint32_t)(st * STG) * 2;
        int row  = lane & 15;
        int half = (lane >> 4) << 3;          // 0 or 8

#pragma unroll
        for (int ks = 0; ks < BK; ks += 16) {
            uint32_t ah[4][4], al[4][4], bh[4][2], bl[4][2];
#pragma unroll
            for (int i = 0; i < 4; i++) {
                uint32_t a = s0 + (uint32_t)((wm + i * 16 + row) * A_STR + ks + half) * 2;
                ldsm4(ah[i], a + AH_OFF * 2);
                ldsm4(al[i], a + AL_OFF * 2);
            }
#pragma unroll
            for (int j = 0; j < 2; j++) {
                uint32_t a = s0 + (uint32_t)((ks + row) * B_STR + wn + j * 16 + half) * 2;
                uint32_t r0, r1, r2, r3;
                ldsm4t(r0, r1, r2, r3, a + BH_OFF * 2);
                bh[2 * j][0] = r0; bh[2 * j][1] = r1;
                bh[2 * j + 1][0] = r2; bh[2 * j + 1][1] = r3;
                ldsm4t(r0, r1, r2, r3, a + BL_OFF * 2);
                bl[2 * j][0] = r0; bl[2 * j][1] = r1;
                bl[2 * j + 1][0] = r2; bl[2 * j + 1][1] = r3;
            }
#pragma unroll
            for (int i = 0; i < 4; i++)
#pragma unroll
                for (int j = 0; j < 4; j++)
                    mma16816(acc[i][j], ah[i], bh[j]);
#pragma unroll
            for (int i = 0; i < 4; i++)
#pragma unroll
                for (int j = 0; j < 4; j++)
                    mma16816(acc[i][j], ah[i], bl[j]);
#pragma unroll
            for (int i = 0; i < 4; i++)
#pragma unroll
                for (int j = 0; j < 4; j++)
                    mma16816(acc[i][j], al[i], bh[j]);
        }
        __syncthreads();
    }

    // --- epilogue: add bias, write Y ---
    int r  = lane >> 2;
    int c2 = (lane & 3) << 1;
#pragma unroll
    for (int i = 0; i < 4; i++) {
        int m0 = bm + wm + i * 16 + r;
        float b0 = bias[m0];
        float b1 = bias[m0 + 8];
        float* y0 = Y + ((size_t)b * COUT + m0) * HW + bn + wn + c2;
        float* y1 = y0 + (size_t)8 * HW;
#pragma unroll
        for (int j = 0; j < 4; j++) {
            float2 v0 = make_float2(acc[i][j][0] + b0, acc[i][j][1] + b0);
            float2 v1 = make_float2(acc[i][j][2] + b1, acc[i][j][3] + b1);
            *(float2*)(y0 + j * 8) = v0;
            *(float2*)(y1 + j * 8) = v1;
        }
    }
}

// ============================================================================
// Kernel D: BN stats
// ============================================================================
__global__ void bnstats_kernel(const float* __restrict__ Y) {
    int o = blockIdx.x;
    int tid = threadIdx.x;
    float s = 0.f, s2 = 0.f;
    for (int b = 0; b < B_; b++) {
        const float* p = Y + ((size_t)b * COUT + o) * HW;
        for (int n = tid; n < HW; n += 256) {
            float v = p[n];
            s += v;
            s2 = fmaf(v, v, s2);
        }
    }
    __shared__ float sh[256], sh2[256];
    sh[tid] = s; sh2[tid] = s2;
    __syncthreads();
    for (int st = 128; st > 0; st >>= 1) {
        if (tid < st) { sh[tid] += sh[tid + st]; sh2[tid] += sh2[tid + st]; }
        __syncthreads();
    }
    if (tid == 0) {
        const float invN = 1.f / (float)(B_ * HW);
        float m   = sh[0] * invN;
        float var = sh2[0] * invN - m * m;
        g_mean[o] = m;
        g_rstd[o] = rsqrtf(var + 1e-5f);
    }
}

// ============================================================================
// Kernel E: normalize + affine + SiLU (in place, float4)
// ============================================================================
__global__ void bnsilu_kernel(float* __restrict__ Y,
                              const float* __restrict__ gamma,
                              const float* __restrict__ beta) {
    size_t i4 = (size_t)blockIdx.x * blockDim.x + threadIdx.x;
    int o = (int)((i4 >> 10) & (COUT - 1));
    float m = g_mean[o], r = g_rstd[o], g = gamma[o], be = beta[o];
    float4 v = ((float4*)Y)[i4];
    float t;
    t = (v.x - m) * r * g + be; v.x = t / (1.f + expf(-t));
    t = (v.y - m) * r * g + be; v.y = t / (1.f + expf(-t));
    t = (v.z - m) * r * g + be; v.z = t / (1.f + expf(-t));
    t = (v.w - m) * r * g + be; v.w = t / (1.f + expf(-t));
    ((float4*)Y)[i4] = v;
}

// ============================================================================
// Launch
// ============================================================================
extern "C" void kernel_launch(void* const* d_in, const int* in_sizes, int n_in,
                              void* d_out, int out_size) {
    const float* x        = (const float*)d_in[0];
    const float* offset_w = (const float*)d_in[1];
    const float* offset_b = (const float*)d_in[2];
    const float* dconv_w  = (const float*)d_in[3];
    const float* dconv_b  = (const float*)d_in[4];
    const float* bn_gamma = (const float*)d_in[5];
    const float* bn_beta  = (const float*)d_in[6];
    float* out = (float*)d_out;

    __nv_bfloat16 *Phi, *Plo, *Whi, *Wlo;
    cudaGetSymbolAddress((void**)&Phi, g_Phi);
    cudaGetSymbolAddress((void**)&Plo, g_Plo);
    cudaGetSymbolAddress((void**)&Whi, g_Whi);
    cudaGetSymbolAddress((void**)&Wlo, g_Wlo);

    static bool attr_set = false;
    if (!attr_set) {
        cudaFuncSetAttribute(offset_conv_kernel,
                             cudaFuncAttributeMaxDynamicSharedMemorySize,
                             OC18 * KD * (int)sizeof(float));
        cudaFuncSetAttribute(gemm_mma_kernel,
                             cudaFuncAttributeMaxDynamicSharedMemorySize,
                             SMEM_GEMM);
        attr_set = true;
    }

    // A: offset conv
    offset_conv_kernel<<<256, 128, OC18 * KD * sizeof(float)>>>(x, offset_w, offset_b);

    // B2: split weights to bf16 hi/lo
    wsplit_kernel<<<(COUT * KD) / 256, 256>>>(dconv_w, Whi, Wlo);

    // B: gather (writes bf16 hi/lo P)
    gather_kernel<<<(B_ * KK9 * HW) / 256, 256>>>(x, Phi, Plo);

    // C: tensor-core (HMMA) GEMM
    dim3 g(HW / 128, COUT / 128, B_);
    gemm_mma_kernel<<<g, 256, SMEM_GEMM>>>(Whi, Wlo, Phi, Plo, dconv_b, out);

    // D: BN stats
    bnstats_kernel<<<COUT, 256>>>(out);

    // E: normalize + SiLU
    bnsilu_kernel<<<(B_ * COUT * HW / 4) / 256, 256>>>(out, bn_gamma, bn_beta);
}

// round 4
// speedup vs baseline: 1.8692x; 1.2498x over previous
#include <cuda_runtime.h>
#include <cuda_bf16.h>
#include <math.h>
#include <cstdint>

// Problem constants
#define B_    8
#define CIN   128
#define H_    64
#define W_    64
#define HW    (H_ * W_)        // 4096
#define COUT  256
#define KK9   9
#define OC18  18
#define KD    (CIN * KK9)      // 1152
#define NCHK  4                // offset-conv channel chunks
#define CCH   (CIN / NCHK)     // 32

// ---------------- scratch (device globals; no allocation allowed) -----------
__device__ float g_offp[NCHK * B_ * OC18 * HW];               // offset partials
__device__ __nv_bfloat16 g_Phi[(size_t)B_ * KD * HW];         // P hi [b][k][n]
__device__ __nv_bfloat16 g_Plo[(size_t)B_ * KD * HW];         // P lo
__device__ __nv_bfloat16 g_Whi[COUT * KD];                    // W hi [m][k]
__device__ __nv_bfloat16 g_Wlo[COUT * KD];
__device__ float g_mean[COUT];
__device__ float g_rstd[COUT];

// ============================================================================
// PTX helpers (plain sm_80+ instructions — compile for compute_103)
// ============================================================================
__device__ __forceinline__ uint32_t smem_u32(const void* p) {
    uint32_t a;
    asm("{ .reg .u64 t; cvta.to.shared.u64 t, %1; cvt.u32.u64 %0, t; }"
        : "=r"(a) : "l"(p));
    return a;
}
__device__ __forceinline__ void cpa16(uint32_t s, const void* g) {
    asm volatile("cp.async.cg.shared.global [%0], [%1], 16;" :: "r"(s), "l"(g));
}
#define CPA_COMMIT() asm volatile("cp.async.commit_group;" ::: "memory")
#define CPA_WAIT(N)  asm volatile("cp.async.wait_group %0;" :: "n"(N) : "memory")

__device__ __forceinline__ void ldsm4(uint32_t* r, uint32_t a) {
    asm volatile("ldmatrix.sync.aligned.m8n8.x4.shared.b16 {%0,%1,%2,%3}, [%4];"
                 : "=r"(r[0]), "=r"(r[1]), "=r"(r[2]), "=r"(r[3]) : "r"(a));
}
__device__ __forceinline__ void ldsm4t(uint32_t& r0, uint32_t& r1,
                                       uint32_t& r2, uint32_t& r3, uint32_t a) {
    asm volatile("ldmatrix.sync.aligned.m8n8.x4.trans.shared.b16 {%0,%1,%2,%3}, [%4];"
                 : "=r"(r0), "=r"(r1), "=r"(r2), "=r"(r3) : "r"(a));
}
__device__ __forceinline__ void mma16816(float* d, const uint32_t* a,
                                         const uint32_t* b) {
    asm volatile(
        "mma.sync.aligned.m16n8k16.row.col.f32.bf16.bf16.f32 "
        "{%0,%1,%2,%3}, {%4,%5,%6,%7}, {%8,%9}, {%0,%1,%2,%3};"
        : "+f"(d[0]), "+f"(d[1]), "+f"(d[2]), "+f"(d[3])
        : "r"(a[0]), "r"(a[1]), "r"(a[2]), "r"(a[3]), "r"(b[0]), "r"(b[1]));
}

// ============================================================================
// Kernel A: offset conv partials. Grid (256 pixel-blocks, 4 channel-chunks).
// Each block: 128 pixels x 32 channels -> partial acc for all 18 outputs.
// ============================================================================
__global__ void offset_conv_part_kernel(const float* __restrict__ x,
                                        const float* __restrict__ w) {
    __shared__ float ws[OC18 * CCH * 9];    // 20736 B
    int cc = blockIdx.y;
    for (int i = threadIdx.x; i < OC18 * CCH * 9; i += blockDim.x) {
        int oc = i / (CCH * 9);
        int r  = i - oc * (CCH * 9);
        ws[i] = w[oc * KD + cc * (CCH * 9) + r];
    }
    __syncthreads();

    int gid = blockIdx.x * blockDim.x + threadIdx.x;   // < 32768
    int b   = gid >> 12;
    int pix = gid & 4095;
    int y   = pix >> 6;
    int xx  = pix & 63;

    float acc[OC18];
#pragma unroll
    for (int oc = 0; oc < OC18; oc++) acc[oc] = 0.f;

    const float* xb = x + (size_t)b * CIN * HW + (size_t)cc * CCH * HW;
    for (int c = 0; c < CCH; c++) {
        const float* xc = xb + (size_t)c * HW;
        float v[9];
#pragma unroll
        for (int ky = 0; ky < 3; ky++) {
            int yy = y - 1 + ky;
            bool yv = (unsigned)yy < (unsigned)H_;
#pragma unroll
            for (int kx = 0; kx < 3; kx++) {
                int x2 = xx - 1 + kx;
                bool xv = (unsigned)x2 < (unsigned)W_;
                v[ky * 3 + kx] = (yv && xv) ? xc[yy * W_ + x2] : 0.f;
            }
        }
#pragma unroll
        for (int kk = 0; kk < 9; kk++) {
            float xvv = v[kk];
#pragma unroll
            for (int oc = 0; oc < OC18; oc++)
                acc[oc] = fmaf(xvv, ws[oc * (CCH * 9) + c * 9 + kk], acc[oc]);
        }
    }

    float* ob = g_offp + (((size_t)cc * B_ + b) * OC18) * HW + pix;
#pragma unroll
    for (int oc = 0; oc < OC18; oc++) ob[(size_t)oc * HW] = acc[oc];
}

// ============================================================================
// Kernel B: deformable bilinear gather -> P_hi/P_lo (bf16 split) [b][k][n]
// Sums the 4 offset partials + bias inline.
// ============================================================================
__global__ void gather_kernel(const float* __restrict__ x,
                              const float* __restrict__ offset_b,
                              __nv_bfloat16* __restrict__ Phi,
                              __nv_bfloat16* __restrict__ Plo) {
    int gid = blockIdx.x * blockDim.x + threadIdx.x;
    int n   = gid & 4095;
    int t   = gid >> 12;
    int kk  = t % 9;
    int b   = t / 9;
    int y   = n >> 6;
    int xx  = n & 63;

    float dy = offset_b[2 * kk + 0];
    float dx = offset_b[2 * kk + 1];
#pragma unroll
    for (int p = 0; p < NCHK; p++) {
        const float* ob = g_offp + (((size_t)p * B_ + b) * OC18) * HW + n;
        dy += ob[(size_t)(2 * kk + 0) * HW];
        dx += ob[(size_t)(2 * kk + 1) * HW];
    }

    float sy = (float)(y - 1 + kk / 3) + dy;
    float sx = (float)(xx - 1 + kk % 3) + dx;

    float fy = floorf(sy), fx = floorf(sx);
    int y0 = (int)fy, x0 = (int)fx;
    int y1 = y0 + 1, x1 = x0 + 1;
    float wy = sy - fy, wx = sx - fx;

    bool vy0 = (unsigned)y0 < (unsigned)H_;
    bool vy1 = (unsigned)y1 < (unsigned)H_;
    bool vx0 = (unsigned)x0 < (unsigned)W_;
    bool vx1 = (unsigned)x1 < (unsigned)W_;

    int cy0 = min(max(y0, 0), H_ - 1), cy1 = min(max(y1, 0), H_ - 1);
    int cx0 = min(max(x0, 0), W_ - 1), cx1 = min(max(x1, 0), W_ - 1);

    int i00 = cy0 * W_ + cx0;
    int i01 = cy0 * W_ + cx1;
    int i10 = cy1 * W_ + cx0;
    int i11 = cy1 * W_ + cx1;

    float w00 = (1.f - wy) * (1.f - wx) * (float)(vy0 && vx0);
    float w01 = (1.f - wy) * wx         * (float)(vy0 && vx1);
    float w10 = wy * (1.f - wx)         * (float)(vy1 && vx0);
    float w11 = wy * wx                 * (float)(vy1 && vx1);

    const float* xb = x + (size_t)b * CIN * HW;
    size_t base = ((size_t)b * KD + kk) * HW + n;

#pragma unroll 4
    for (int c = 0; c < CIN; c++) {
        const float* xc = xb + (size_t)c * HW;
        float v = w00 * xc[i00] + w01 * xc[i01] + w10 * xc[i10] + w11 * xc[i11];
        __nv_bfloat16 h = __float2bfloat16(v);
        float lo = v - __bfloat162float(h);
        size_t idx = base + (size_t)c * (KK9 * HW);
        Phi[idx] = h;
        Plo[idx] = __float2bfloat16(lo);
    }
}

// ============================================================================
// Kernel B2: split dconv weights into bf16 hi/lo
// ============================================================================
__global__ void wsplit_kernel(const float* __restrict__ w,
                              __nv_bfloat16* __restrict__ hi,
                              __nv_bfloat16* __restrict__ lo) {
    int i = blockIdx.x * blockDim.x + threadIdx.x;
    float v = w[i];
    __nv_bfloat16 h = __float2bfloat16(v);
    hi[i] = h;
    lo[i] = __float2bfloat16(v - __bfloat162float(h));
}

// ============================================================================
// Kernel C: HMMA GEMM  Y[b] = W[256,1152] @ P[b][1152,4096] + bias
// bf16 hi/lo 3-pass (Ah*Bh + Ah*Bl + Al*Bh), fp32 accum.
// CTA 128x128, BK=32, 512 threads (16 warps, 4x4 grid, warp tile 32x32),
// 3-stage cp.async pipeline.
// ============================================================================
#define BK      32
#define NC      (KD / BK)        // 36
#define A_STR   40               // padded bf16 per A row
#define B_STR   136              // padded bf16 per B row
#define AH_OFF  0
#define AL_OFF  (128 * A_STR)                // 5120
#define BH_OFF  (2 * 128 * A_STR)            // 10240
#define BL_OFF  (BH_OFF + 32 * B_STR)        // 14592
#define STG     (BL_OFF + 32 * B_STR)        // 18944 bf16 per stage
#define NSTAGE  3
#define SMEM_GEMM (NSTAGE * STG * 2)         // 113664 bytes

__global__ void __launch_bounds__(512, 1)
gemm_mma_kernel(const __nv_bfloat16* __restrict__ Whi,
                const __nv_bfloat16* __restrict__ Wlo,
                const __nv_bfloat16* __restrict__ Phi,
                const __nv_bfloat16* __restrict__ Plo,
                const float* __restrict__ bias,
                float* __restrict__ Y) {
    extern __shared__ __nv_bfloat16 sm[];
    const uint32_t sbase = smem_u32(sm);

    int tid  = threadIdx.x;
    int wid  = tid >> 5;
    int lane = tid & 31;
    int bn = blockIdx.x * 128;
    int bm = blockIdx.y * 128;
    int b  = blockIdx.z;

    int wm = (wid >> 2) * 32;    // warp m offset
    int wn = (wid & 3) * 32;     // warp n offset

    const __nv_bfloat16* PbH = Phi + (size_t)b * KD * HW;
    const __nv_bfloat16* PbL = Plo + (size_t)b * KD * HW;

    float acc[2][4][4];
#pragma unroll
    for (int i = 0; i < 2; i++)
#pragma unroll
        for (int j = 0; j < 4; j++)
#pragma unroll
            for (int q = 0; q < 4; q++) acc[i][j][q] = 0.f;

    // --- async stage loader: 512 threads, 4 cp.async each ---
    auto load_stage = [&](int chunk, int st) {
        int k0 = chunk * BK;
        uint32_t s0 = sbase + (uint32_t)(st * STG) * 2;
        {   // A: 128 rows x 32 k, hi+lo
            int m  = tid >> 2;
            int kq = (tid & 3) << 3;
            size_t go = (size_t)(bm + m) * KD + k0 + kq;
            uint32_t sa = s0 + (uint32_t)(m * A_STR + kq) * 2;
            cpa16(sa + AH_OFF * 2, Whi + go);
            cpa16(sa + AL_OFF * 2, Wlo + go);
        }
        {   // B: 32 k-rows x 128 n, hi+lo
            int k  = tid >> 4;
            int nq = (tid & 15) << 3;
            size_t go = (size_t)(k0 + k) * HW + bn + nq;
            uint32_t sa = s0 + (uint32_t)(k * B_STR + nq) * 2;
            cpa16(sa + BH_OFF * 2, PbH + go);
            cpa16(sa + BL_OFF * 2, PbL + go);
        }
        CPA_COMMIT();
    };

    load_stage(0, 0);
    load_stage(1, 1);

    int row  = lane & 15;
    int half = (lane >> 4) << 3;          // 0 or 8

    for (int c = 0; c < NC; c++) {
        int st = c % NSTAGE;
        if (c + 2 < NC) {
            load_stage(c + 2, (c + 2) % NSTAGE);
            CPA_WAIT(2);
        } else if (c + 1 < NC) {
            CPA_WAIT(1);
        } else {
            CPA_WAIT(0);
        }
        __syncthreads();

        uint32_t s0 = sbase + (uint32_t)(st * STG) * 2;

#pragma unroll
        for (int ks = 0; ks < BK; ks += 16) {
            uint32_t ah[2][4], al[2][4], bh[4][2], bl[4][2];
#pragma unroll
            for (int i = 0; i < 2; i++) {
                uint32_t a = s0 + (uint32_t)((wm + i * 16 + row) * A_STR + ks + half) * 2;
                ldsm4(ah[i], a + AH_OFF * 2);
                ldsm4(al[i], a + AL_OFF * 2);
            }
#pragma unroll
            for (int j = 0; j < 2; j++) {
                uint32_t a = s0 + (uint32_t)((ks + row) * B_STR + wn + j * 16 + half) * 2;
                uint32_t r0, r1, r2, r3;
                ldsm4t(r0, r1, r2, r3, a + BH_OFF * 2);
                bh[2 * j][0] = r0; bh[2 * j][1] = r1;
                bh[2 * j + 1][0] = r2; bh[2 * j + 1][1] = r3;
                ldsm4t(r0, r1, r2, r3, a + BL_OFF * 2);
                bl[2 * j][0] = r0; bl[2 * j][1] = r1;
                bl[2 * j + 1][0] = r2; bl[2 * j + 1][1] = r3;
            }
#pragma unroll
            for (int i = 0; i < 2; i++)
#pragma unroll
                for (int j = 0; j < 4; j++)
                    mma16816(acc[i][j], ah[i], bh[j]);
#pragma unroll
            for (int i = 0; i < 2; i++)
#pragma unroll
                for (int j = 0; j < 4; j++)
                    mma16816(acc[i][j], ah[i], bl[j]);
#pragma unroll
            for (int i = 0; i < 2; i++)
#pragma unroll
                for (int j = 0; j < 4; j++)
                    mma16816(acc[i][j], al[i], bh[j]);
        }
        __syncthreads();
    }

    // --- epilogue: add bias, write Y ---
    int r  = lane >> 2;
    int c2 = (lane & 3) << 1;
#pragma unroll
    for (int i = 0; i < 2; i++) {
        int m0 = bm + wm + i * 16 + r;
        float b0 = bias[m0];
        float b1 = bias[m0 + 8];
        float* y0 = Y + ((size_t)b * COUT + m0) * HW + bn + wn + c2;
        float* y1 = y0 + (size_t)8 * HW;
#pragma unroll
        for (int j = 0; j < 4; j++) {
            float2 v0 = make_float2(acc[i][j][0] + b0, acc[i][j][1] + b0);
            float2 v1 = make_float2(acc[i][j][2] + b1, acc[i][j][3] + b1);
            *(float2*)(y0 + j * 8) = v0;
            *(float2*)(y1 + j * 8) = v1;
        }
    }
}

// ============================================================================
// Kernel D: BN stats (float4 vectorized)
// ============================================================================
__global__ void bnstats_kernel(const float* __restrict__ Y) {
    int o = blockIdx.x;
    int tid = threadIdx.x;
    float s = 0.f, s2 = 0.f;
    for (int b = 0; b < B_; b++) {
        const float4* p = (const float4*)(Y + ((size_t)b * COUT + o) * HW);
        for (int n = tid; n < HW / 4; n += 256) {
            float4 v = p[n];
            s += v.x + v.y + v.z + v.w;
            s2 = fmaf(v.x, v.x, s2);
            s2 = fmaf(v.y, v.y, s2);
            s2 = fmaf(v.z, v.z, s2);
            s2 = fmaf(v.w, v.w, s2);
        }
    }
    __shared__ float sh[256], sh2[256];
    sh[tid] = s; sh2[tid] = s2;
    __syncthreads();
    for (int st = 128; st > 0; st >>= 1) {
        if (tid < st) { sh[tid] += sh[tid + st]; sh2[tid] += sh2[tid + st]; }
        __syncthreads();
    }
    if (tid == 0) {
        const float invN = 1.f / (float)(B_ * HW);
        float m   = sh[0] * invN;
        float var = sh2[0] * invN - m * m;
        g_mean[o] = m;
        g_rstd[o] = rsqrtf(var + 1e-5f);
    }
}

// ============================================================================
// Kernel E: normalize + affine + SiLU (in place, float4, fast exp)
// ============================================================================
__global__ void bnsilu_kernel(float* __restrict__ Y,
                              const float* __restrict__ gamma,
                              const float* __restrict__ beta) {
    size_t i4 = (size_t)blockIdx.x * blockDim.x + threadIdx.x;
    int o = (int)((i4 >> 10) & (COUT - 1));
    float m = g_mean[o], r = g_rstd[o], g = gamma[o], be = beta[o];
    float4 v = ((float4*)Y)[i4];
    float t;
    t = (v.x - m) * r * g + be; v.x = t / (1.f + __expf(-t));
    t = (v.y - m) * r * g + be; v.y = t / (1.f + __expf(-t));
    t = (v.z - m) * r * g + be; v.z = t / (1.f + __expf(-t));
    t = (v.w - m) * r * g + be; v.w = t / (1.f + __expf(-t));
    ((float4*)Y)[i4] = v;
}

// ============================================================================
// Launch
// ============================================================================
extern "C" void kernel_launch(void* const* d_in, const int* in_sizes, int n_in,
                              void* d_out, int out_size) {
    const float* x        = (const float*)d_in[0];
    const float* offset_w = (const float*)d_in[1];
    const float* offset_b = (const float*)d_in[2];
    const float* dconv_w  = (const float*)d_in[3];
    const float* dconv_b  = (const float*)d_in[4];
    const float* bn_gamma = (const float*)d_in[5];
    const float* bn_beta  = (const float*)d_in[6];
    float* out = (float*)d_out;

    __nv_bfloat16 *Phi, *Plo, *Whi, *Wlo;
    cudaGetSymbolAddress((void**)&Phi, g_Phi);
    cudaGetSymbolAddress((void**)&Plo, g_Plo);
    cudaGetSymbolAddress((void**)&Whi, g_Whi);
    cudaGetSymbolAddress((void**)&Wlo, g_Wlo);

    static bool attr_set = false;
    if (!attr_set) {
        cudaFuncSetAttribute(gemm_mma_kernel,
                             cudaFuncAttributeMaxDynamicSharedMemorySize,
                             SMEM_GEMM);
        attr_set = true;
    }

    // A: offset conv partials (4 channel chunks)
    offset_conv_part_kernel<<<dim3(256, NCHK), 128>>>(x, offset_w);

    // B2: split weights to bf16 hi/lo
    wsplit_kernel<<<(COUT * KD) / 256, 256>>>(dconv_w, Whi, Wlo);

    // B: gather (sums offset partials + bias; writes bf16 hi/lo P)
    gather_kernel<<<(B_ * KK9 * HW) / 256, 256>>>(x, offset_b, Phi, Plo);

    // C: tensor-core (HMMA) GEMM
    dim3 g(HW / 128, COUT / 128, B_);
    gemm_mma_kernel<<<g, 512, SMEM_GEMM>>>(Whi, Wlo, Phi, Plo, dconv_b, out);

    // D: BN stats
    bnstats_kernel<<<COUT, 256>>>(out);

    // E: normalize + SiLU
    bnsilu_kernel<<<(B_ * COUT * HW / 4) / 256, 256>>>(out, bn_gamma, bn_beta);
}